// round 2
// baseline (speedup 1.0000x reference)
#include <cuda_runtime.h>
#include <math.h>

#define NEXP  8
#define DDIM  2048
#define FDIM  1024
#define MAXT  2048
#define MAXSLOT (2*MAXT)

#define TM 128
#define TN 128
#define TKK 16
#define PAD 4

// ---------------- scratch (device globals; no runtime allocation) ----------
__device__ int   g_cnt[NEXP];
__device__ int   g_off[NEXP];
__device__ int   g_list[NEXP*MAXT];
__device__ float g_wt[NEXP*MAXT];
__device__ float g_h[(size_t)MAXSLOT*FDIM];   // 16 MB: silu(g)*u activations

// ---------------- f32x2 helpers (Blackwell packed fp32) ---------------------
__device__ __forceinline__ void fma2(unsigned long long &d, unsigned long long a,
                                     unsigned long long b) {
    asm("fma.rn.f32x2 %0, %1, %2, %3;" : "=l"(d) : "l"(a), "l"(b), "l"(d));
}
__device__ __forceinline__ unsigned long long pack2(float lo, float hi) {
    unsigned long long r;
    asm("mov.b64 %0, {%1, %2};" : "=l"(r) : "f"(lo), "f"(hi));
    return r;
}
__device__ __forceinline__ float2 unpack2(unsigned long long v) {
    float2 r;
    asm("mov.b64 {%0, %1}, %2;" : "=f"(r.x), "=f"(r.y) : "l"(v));
    return r;
}

// ---------------- zero output + reset counters ------------------------------
__global__ void zero_kernel(float* __restrict__ out, int n) {
    int i = (blockIdx.x * blockDim.x + threadIdx.x) * 4;
    if (i + 3 < n) {
        *(float4*)(out + i) = make_float4(0.f, 0.f, 0.f, 0.f);
    } else {
        for (int j = i; j < n; j++) out[j] = 0.f;
    }
    if (blockIdx.x == 0 && threadIdx.x < NEXP) g_cnt[threadIdx.x] = 0;
}

// ---------------- router: logits, softmax, top-2, bucket --------------------
__global__ void router_kernel(const float* __restrict__ x,
                              const float* __restrict__ gw,
                              float* __restrict__ logits_out,
                              int write_logits) {
    __shared__ float xs[DDIM];
    __shared__ float lg[NEXP];
    int t = blockIdx.x;
    const float* xr = x + (size_t)t * DDIM;
    for (int i = threadIdx.x; i < DDIM; i += blockDim.x) xs[i] = xr[i];
    __syncthreads();

    int w = threadIdx.x >> 5, lane = threadIdx.x & 31;
    if (w < NEXP) {
        const float* g = gw + (size_t)w * DDIM;
        float s = 0.f;
        for (int d = lane; d < DDIM; d += 32) s = fmaf(xs[d], g[d], s);
        for (int o = 16; o; o >>= 1) s += __shfl_xor_sync(0xffffffffu, s, o);
        if (lane == 0) lg[w] = s;
    }
    __syncthreads();

    if (threadIdx.x == 0) {
        float l[NEXP], p[NEXP];
        float m = -1e30f;
        for (int e = 0; e < NEXP; e++) {
            l[e] = lg[e];
            if (write_logits) logits_out[(size_t)t * NEXP + e] = l[e];
            m = fmaxf(m, l[e]);
        }
        float se = 0.f;
        for (int e = 0; e < NEXP; e++) { p[e] = expf(l[e] - m); se += p[e]; }
        float inv = 1.f / se;
        for (int e = 0; e < NEXP; e++) p[e] *= inv;
        // top-2, ties -> lowest index (matches lax.top_k)
        int i1 = 0;
        for (int e = 1; e < NEXP; e++) if (p[e] > p[i1]) i1 = e;
        int i2 = -1;
        for (int e = 0; e < NEXP; e++) {
            if (e == i1) continue;
            if (i2 < 0 || p[e] > p[i2]) i2 = e;
        }
        float s12 = p[i1] + p[i2];
        float w1 = p[i1] / s12, w2 = p[i2] / s12;
        int p1 = atomicAdd(&g_cnt[i1], 1);
        g_list[i1 * MAXT + p1] = t;  g_wt[i1 * MAXT + p1] = w1;
        int p2 = atomicAdd(&g_cnt[i2], 1);
        g_list[i2 * MAXT + p2] = t;  g_wt[i2 * MAXT + p2] = w2;
    }
}

__global__ void prefix_kernel() {
    int o = 0;
    for (int e = 0; e < NEXP; e++) { g_off[e] = o; o += g_cnt[e]; }
}

// ---------------- fused gate+up GEMM + SiLU ---------------------------------
// h[off[e]+r, f] = silu(x[tok] . Wg[e,f,:]) * (x[tok] . Wu[e,f,:])
__global__ __launch_bounds__(256, 1)
void gateup_kernel(const float* __restrict__ x,
                   const float* __restrict__ wg,
                   const float* __restrict__ wu) {
    int e = blockIdx.z;
    int n = g_cnt[e];
    int r0 = blockIdx.y * TM;
    if (r0 >= n) return;
    int f0 = blockIdx.x * TN;

    __shared__ __align__(16) float xs[TKK][TM + PAD];
    __shared__ __align__(16) float gs[TKK][TN + PAD];
    __shared__ __align__(16) float us[TKK][TN + PAD];
    __shared__ int toks[TM];

    if (threadIdx.x < TM) {
        int r = r0 + threadIdx.x;
        toks[threadIdx.x] = (r < n) ? g_list[e * MAXT + r] : -1;
    }
    __syncthreads();

    int tx = threadIdx.x & 15, ty = threadIdx.x >> 4;
    unsigned long long accg[8][4], accu[8][4];
    #pragma unroll
    for (int i = 0; i < 8; i++)
        #pragma unroll
        for (int j = 0; j < 4; j++) { accg[i][j] = 0ull; accu[i][j] = 0ull; }

    const float* wge = wg + (size_t)e * FDIM * DDIM + (size_t)f0 * DDIM;
    const float* wue = wu + (size_t)e * FDIM * DDIM + (size_t)f0 * DDIM;

    for (int k0 = 0; k0 < DDIM; k0 += TKK) {
        #pragma unroll
        for (int i = threadIdx.x; i < TM * TKK; i += 256) {
            int k = i & 15, m = i >> 4;
            int tk = toks[m];
            xs[k][m] = (tk >= 0) ? x[(size_t)tk * DDIM + k0 + k] : 0.f;
        }
        #pragma unroll
        for (int i = threadIdx.x; i < TN * TKK; i += 256) {
            int k = i & 15, f = i >> 4;
            gs[k][f] = wge[(size_t)f * DDIM + k0 + k];
            us[k][f] = wue[(size_t)f * DDIM + k0 + k];
        }
        __syncthreads();

        #pragma unroll
        for (int k = 0; k < TKK; k++) {
            unsigned long long xp[8], gv[4], uv[4];
            #pragma unroll
            for (int i = 0; i < 8; i++) {
                float xv = xs[k][ty * 8 + i];
                xp[i] = pack2(xv, xv);
            }
            const unsigned long long* gp =
                (const unsigned long long*)&gs[k][tx * 8];
            const unsigned long long* up =
                (const unsigned long long*)&us[k][tx * 8];
            #pragma unroll
            for (int j = 0; j < 4; j++) { gv[j] = gp[j]; uv[j] = up[j]; }
            #pragma unroll
            for (int i = 0; i < 8; i++)
                #pragma unroll
                for (int j = 0; j < 4; j++) {
                    fma2(accg[i][j], xp[i], gv[j]);
                    fma2(accu[i][j], xp[i], uv[j]);
                }
        }
        __syncthreads();
    }

    int hbase = g_off[e];
    #pragma unroll
    for (int i = 0; i < 8; i++) {
        int r = r0 + ty * 8 + i;
        if (r < n) {
            float* hrow = g_h + (size_t)(hbase + r) * FDIM + f0 + tx * 8;
            #pragma unroll
            for (int j = 0; j < 4; j++) {
                float2 g = unpack2(accg[i][j]);
                float2 u = unpack2(accu[i][j]);
                float s0 = g.x / (1.f + expf(-g.x));
                float s1 = g.y / (1.f + expf(-g.y));
                hrow[2 * j + 0] = s0 * u.x;
                hrow[2 * j + 1] = s1 * u.y;
            }
        }
    }
}

// ---------------- down GEMM + weighted scatter ------------------------------
// out[tok, d] += wt * sum_f h[off[e]+r, f] * Wd[e, d, f]
__global__ __launch_bounds__(256, 1)
void down_kernel(const float* __restrict__ wd, float* __restrict__ out) {
    int e = blockIdx.z;
    int n = g_cnt[e];
    int r0 = blockIdx.y * TM;
    if (r0 >= n) return;
    int d0 = blockIdx.x * TN;

    __shared__ __align__(16) float hs[TKK][TM + PAD];
    __shared__ __align__(16) float ws[TKK][TN + PAD];
    __shared__ int   toks[TM];
    __shared__ float wts[TM];

    if (threadIdx.x < TM) {
        int r = r0 + threadIdx.x;
        toks[threadIdx.x] = (r < n) ? g_list[e * MAXT + r] : -1;
        wts[threadIdx.x]  = (r < n) ? g_wt[e * MAXT + r] : 0.f;
    }
    __syncthreads();

    int tx = threadIdx.x & 15, ty = threadIdx.x >> 4;
    unsigned long long acc[8][4];
    #pragma unroll
    for (int i = 0; i < 8; i++)
        #pragma unroll
        for (int j = 0; j < 4; j++) acc[i][j] = 0ull;

    const float* wde = wd + (size_t)e * DDIM * FDIM + (size_t)d0 * FDIM;
    int hbase = g_off[e];

    for (int k0 = 0; k0 < FDIM; k0 += TKK) {
        #pragma unroll
        for (int i = threadIdx.x; i < TM * TKK; i += 256) {
            int k = i & 15, m = i >> 4;
            int r = r0 + m;
            hs[k][m] = (r < n) ? g_h[(size_t)(hbase + r) * FDIM + k0 + k] : 0.f;
        }
        #pragma unroll
        for (int i = threadIdx.x; i < TN * TKK; i += 256) {
            int k = i & 15, d = i >> 4;
            ws[k][d] = wde[(size_t)d * FDIM + k0 + k];
        }
        __syncthreads();

        #pragma unroll
        for (int k = 0; k < TKK; k++) {
            unsigned long long hp[8], wv[4];
            #pragma unroll
            for (int i = 0; i < 8; i++) {
                float hv = hs[k][ty * 8 + i];
                hp[i] = pack2(hv, hv);
            }
            const unsigned long long* wp =
                (const unsigned long long*)&ws[k][tx * 8];
            #pragma unroll
            for (int j = 0; j < 4; j++) wv[j] = wp[j];
            #pragma unroll
            for (int i = 0; i < 8; i++)
                #pragma unroll
                for (int j = 0; j < 4; j++) fma2(acc[i][j], hp[i], wv[j]);
        }
        __syncthreads();
    }

    #pragma unroll
    for (int i = 0; i < 8; i++) {
        int r = r0 + ty * 8 + i;
        if (r < n) {
            int   tk = toks[ty * 8 + i];
            float w  = wts[ty * 8 + i];
            float* orow = out + (size_t)tk * DDIM + d0 + tx * 8;
            #pragma unroll
            for (int j = 0; j < 4; j++) {
                float2 v = unpack2(acc[i][j]);
                atomicAdd(&orow[2 * j + 0], v.x * w);
                atomicAdd(&orow[2 * j + 1], v.y * w);
            }
        }
    }
}

// ---------------- launch ----------------------------------------------------
extern "C" void kernel_launch(void* const* d_in, const int* in_sizes, int n_in,
                              void* d_out, int out_size) {
    const float* x  = (const float*)d_in[0];   // hidden_states [B,S,D]
    const float* gw = (const float*)d_in[1];   // gate_w [E,D]
    const float* wg = (const float*)d_in[2];   // w_gate_proj [E,F,D]
    const float* wu = (const float*)d_in[3];   // w_up_proj [E,F,D]
    const float* wd = (const float*)d_in[4];   // w_down_proj [E,D,F]
    float* out = (float*)d_out;

    int T = in_sizes[0] / DDIM;                // tokens
    int write_logits = (out_size >= T * DDIM + T * NEXP) ? 1 : 0;
    float* logits = out + (size_t)T * DDIM;

    int nzero = out_size;
    int zblocks = ((nzero + 3) / 4 + 255) / 256;
    zero_kernel<<<zblocks, 256>>>(out, nzero);

    router_kernel<<<T, 256>>>(x, gw, logits, write_logits);
    prefix_kernel<<<1, 1>>>();

    dim3 gg(FDIM / TN, (T + TM - 1) / TM, NEXP);
    gateup_kernel<<<gg, 256>>>(x, wg, wu);

    dim3 gd(DDIM / TN, (T + TM - 1) / TM, NEXP);
    down_kernel<<<gd, 256>>>(wd, out);
}

// round 4
// speedup vs baseline: 2.1249x; 2.1249x over previous
#include <cuda_runtime.h>
#include <cuda_fp16.h>
#include <math.h>
#include <stdint.h>

#define NEXP 8
#define DDIM 2048
#define FDIM 1024
#define MAXT 2048
#define MAXSLOT (2*MAXT)
#define PITCH 40   // halves per 32-k row (64B data + 16B pad)

// ---------------- device scratch --------------------------------------------
__device__ int   g_cnt[NEXP];
__device__ int   g_off[NEXP];
__device__ int   g_list[NEXP*MAXT];
__device__ int   g_te[2*MAXT];
__device__ int   g_tp[2*MAXT];
__device__ float g_tw[2*MAXT];
__device__ __half g_xh[(size_t)MAXT*DDIM];
__device__ __half g_xl[(size_t)MAXT*DDIM];
__device__ __half g_hh[(size_t)MAXSLOT*FDIM];
__device__ __half g_hl[(size_t)MAXSLOT*FDIM];
__device__ float  g_y[(size_t)MAXSLOT*DDIM];

// ---------------- helpers ----------------------------------------------------
__device__ __forceinline__ uint32_t s2u(const void* p) {
    return (uint32_t)__cvta_generic_to_shared(p);
}
__device__ __forceinline__ void ldsm4(uint32_t* r, uint32_t a) {
    asm volatile("ldmatrix.sync.aligned.m8n8.x4.shared.b16 {%0,%1,%2,%3}, [%4];"
                 : "=r"(r[0]), "=r"(r[1]), "=r"(r[2]), "=r"(r[3]) : "r"(a));
}
__device__ __forceinline__ void mma16816(float* c, const uint32_t* a,
                                         const uint32_t* b) {
    asm volatile(
        "mma.sync.aligned.m16n8k16.row.col.f32.f16.f16.f32 "
        "{%0,%1,%2,%3}, {%4,%5,%6,%7}, {%8,%9}, {%0,%1,%2,%3};"
        : "+f"(c[0]), "+f"(c[1]), "+f"(c[2]), "+f"(c[3])
        : "r"(a[0]), "r"(a[1]), "r"(a[2]), "r"(a[3]), "r"(b[0]), "r"(b[1]));
}
__device__ __forceinline__ void cp16(uint32_t dst, const void* src, int sz) {
    asm volatile("cp.async.ca.shared.global [%0], [%1], 16, %2;"
                 :: "r"(dst), "l"(src), "r"(sz) : "memory");
}
__device__ __forceinline__ void cp_commit() {
    asm volatile("cp.async.commit_group;" ::: "memory");
}
__device__ __forceinline__ void cp_waitall() {
    asm volatile("cp.async.wait_group 0;" ::: "memory");
}
__device__ __forceinline__ uint32_t pack2h(__half a, __half b) {
    return ((uint32_t)__half_as_ushort(b) << 16) | __half_as_ushort(a);
}
// 8 fp32 -> 8 hi halves + 8 lo halves
__device__ __forceinline__ void split8(float4 v0, float4 v1, uint4& h, uint4& l) {
    float f[8] = {v0.x,v0.y,v0.z,v0.w,v1.x,v1.y,v1.z,v1.w};
    uint32_t hh[4], ll[4];
#pragma unroll
    for (int j = 0; j < 4; j++) {
        __half a = __float2half_rn(f[2*j]);
        __half b = __float2half_rn(f[2*j+1]);
        __half ra = __float2half_rn(f[2*j]   - __half2float(a));
        __half rb = __float2half_rn(f[2*j+1] - __half2float(b));
        hh[j] = pack2h(a, b);
        ll[j] = pack2h(ra, rb);
    }
    h = make_uint4(hh[0],hh[1],hh[2],hh[3]);
    l = make_uint4(ll[0],ll[1],ll[2],ll[3]);
}

// ---------------- small kernels ---------------------------------------------
__global__ void reset_kernel() {
    if (threadIdx.x < NEXP) g_cnt[threadIdx.x] = 0;
}

__global__ void presplit_kernel(const float* __restrict__ x, int n4) {
    int i = blockIdx.x * blockDim.x + threadIdx.x;
    if (i >= n4) return;
    float4 v = ((const float4*)x)[i];
    float f[4] = {v.x, v.y, v.z, v.w};
    ushort h[4], l[4];
#pragma unroll
    for (int j = 0; j < 4; j++) {
        __half a = __float2half_rn(f[j]);
        __half r = __float2half_rn(f[j] - __half2float(a));
        h[j] = __half_as_ushort(a);
        l[j] = __half_as_ushort(r);
    }
    ((uint2*)g_xh)[i] = make_uint2(((uint32_t)h[1]<<16)|h[0], ((uint32_t)h[3]<<16)|h[2]);
    ((uint2*)g_xl)[i] = make_uint2(((uint32_t)l[1]<<16)|l[0], ((uint32_t)l[3]<<16)|l[2]);
}

__global__ void router_kernel(const float* __restrict__ x,
                              const float* __restrict__ gw,
                              float* __restrict__ logits_out,
                              int write_logits) {
    __shared__ float xs[DDIM];
    __shared__ float lg[NEXP];
    int t = blockIdx.x;
    const float* xr = x + (size_t)t * DDIM;
    for (int i = threadIdx.x; i < DDIM; i += blockDim.x) xs[i] = xr[i];
    __syncthreads();

    int w = threadIdx.x >> 5, lane = threadIdx.x & 31;
    if (w < NEXP) {
        const float* g = gw + (size_t)w * DDIM;
        float s = 0.f;
        for (int d = lane; d < DDIM; d += 32) s = fmaf(xs[d], g[d], s);
        for (int o = 16; o; o >>= 1) s += __shfl_xor_sync(0xffffffffu, s, o);
        if (lane == 0) lg[w] = s;
    }
    __syncthreads();

    if (threadIdx.x == 0) {
        float l[NEXP], p[NEXP];
        float m = -1e30f;
        for (int e = 0; e < NEXP; e++) {
            l[e] = lg[e];
            if (write_logits) logits_out[(size_t)t * NEXP + e] = l[e];
            m = fmaxf(m, l[e]);
        }
        float se = 0.f;
        for (int e = 0; e < NEXP; e++) { p[e] = expf(l[e] - m); se += p[e]; }
        float inv = 1.f / se;
        for (int e = 0; e < NEXP; e++) p[e] *= inv;
        int i1 = 0;
        for (int e = 1; e < NEXP; e++) if (p[e] > p[i1]) i1 = e;
        int i2 = -1;
        for (int e = 0; e < NEXP; e++) {
            if (e == i1) continue;
            if (i2 < 0 || p[e] > p[i2]) i2 = e;
        }
        float s12 = p[i1] + p[i2];
        float w1 = p[i1] / s12, w2 = p[i2] / s12;
        int p1 = atomicAdd(&g_cnt[i1], 1);
        g_list[i1 * MAXT + p1] = t;
        int p2 = atomicAdd(&g_cnt[i2], 1);
        g_list[i2 * MAXT + p2] = t;
        g_te[2*t] = i1;   g_tp[2*t] = p1;   g_tw[2*t] = w1;
        g_te[2*t+1] = i2; g_tp[2*t+1] = p2; g_tw[2*t+1] = w2;
    }
}

__global__ void prefix_kernel() {
    int o = 0;
    for (int e = 0; e < NEXP; e++) { g_off[e] = o; o += g_cnt[e]; }
}

extern __shared__ __align__(16) char dynsm[];

// ---------------- gate+up HMMA kernel ---------------------------------------
// stage layout (bytes): Ah 0 | Al 10240 | Gh 20480 | Gl 25600 | Uh 30720 | Ul 35840
#define GU_ST 40960
#define GU_DYN (2*GU_ST)

__global__ __launch_bounds__(256)
void gateup_mma(const float* __restrict__ wg, const float* __restrict__ wu) {
    int e = blockIdx.z;
    int n = g_cnt[e];
    int r0 = blockIdx.y * 128;
    if (r0 >= n) return;
    int f0 = blockIdx.x * 64;

    __shared__ int toks[128];
    int tid = threadIdx.x, lane = tid & 31, wid = tid >> 5;
    uint32_t smb = s2u(dynsm);

    if (tid < 128) {
        int r = r0 + tid;
        toks[tid] = (r < n) ? g_list[e * MAXT + r] : -1;
    }
    __syncthreads();

    const float* wge = wg + (size_t)e * FDIM * DDIM + (size_t)f0 * DDIM;
    const float* wue = wu + (size_t)e * FDIM * DDIM + (size_t)f0 * DDIM;

    int arow = tid & 127, aseg = tid >> 7;          // A loader mapping
    int brow = tid & 63, bhalf = (tid >> 6) & 1;    // B loader mapping
    const float* bptr = (tid >= 128 ? wue : wge) + (size_t)brow * DDIM + bhalf * 16;
    int bofs = (tid >= 128 ? 30720 : 20480) + (brow * PITCH + bhalf * 16) * 2;

    auto issueA = [&](int k0, int st) {
        int tk = toks[arow];
        uint32_t d = smb + st * GU_ST + (arow * PITCH + aseg * 16) * 2;
        const __half* sh = g_xh + ((size_t)(tk < 0 ? 0 : tk) * DDIM + k0 + aseg * 16);
        const __half* sl = g_xl + ((size_t)(tk < 0 ? 0 : tk) * DDIM + k0 + aseg * 16);
        int sz = (tk < 0) ? 0 : 16;
        cp16(d,           sh,     sz);
        cp16(d + 16,      sh + 8, sz);
        cp16(d + 10240,      sl,     sz);
        cp16(d + 10240 + 16, sl + 8, sz);
    };
    auto loadB = [&](int k0, float4* v) {
        const float* p = bptr + k0;
        v[0] = ((const float4*)p)[0];
        v[1] = ((const float4*)p)[1];
        v[2] = ((const float4*)p)[2];
        v[3] = ((const float4*)p)[3];
    };
    auto storeB = [&](int st, float4* v) {
        char* d = dynsm + st * GU_ST + bofs;
        uint4 h0, l0, h1, l1;
        split8(v[0], v[1], h0, l0);
        split8(v[2], v[3], h1, l1);
        *(uint4*)(d)              = h0;
        *(uint4*)(d + 16)         = h1;
        *(uint4*)(d + 5120)       = l0;
        *(uint4*)(d + 5120 + 16)  = l1;
    };

    float accG[2][4][4], accU[2][4][4];
#pragma unroll
    for (int mt = 0; mt < 2; mt++)
#pragma unroll
        for (int nt = 0; nt < 4; nt++)
#pragma unroll
            for (int j = 0; j < 4; j++) { accG[mt][nt][j] = 0.f; accU[mt][nt][j] = 0.f; }

    int m0 = (wid & 3) * 32, n0 = (wid >> 2) * 32;
    int mat = lane >> 3, rowin = lane & 7;

    auto compute = [&](int st) {
        uint32_t base = smb + st * GU_ST;
#pragma unroll
        for (int s = 0; s < 2; s++) {
            int kc = s * 16;
            uint32_t ah[2][4], al[2][4];
#pragma unroll
            for (int mt = 0; mt < 2; mt++) {
                uint32_t a = base +
                    ((m0 + mt * 16 + (mat & 1) * 8 + rowin) * PITCH + kc + (mat >> 1) * 8) * 2;
                ldsm4(ah[mt], a);
                ldsm4(al[mt], a + 10240);
            }
            uint32_t bh[8], bl[8];
#pragma unroll
            for (int h16 = 0; h16 < 2; h16++) {
                uint32_t a = base + 20480 +
                    ((n0 + h16 * 16 + (mat >> 1) * 8 + rowin) * PITCH + kc + (mat & 1) * 8) * 2;
                ldsm4(&bh[h16 * 4], a);
                ldsm4(&bl[h16 * 4], a + 5120);
            }
#pragma unroll
            for (int mt = 0; mt < 2; mt++)
#pragma unroll
                for (int nt = 0; nt < 4; nt++) {
                    mma16816(accG[mt][nt], ah[mt], &bh[nt * 2]);
                    mma16816(accG[mt][nt], ah[mt], &bl[nt * 2]);
                    mma16816(accG[mt][nt], al[mt], &bh[nt * 2]);
                }
#pragma unroll
            for (int h16 = 0; h16 < 2; h16++) {
                uint32_t a = base + 30720 +
                    ((n0 + h16 * 16 + (mat >> 1) * 8 + rowin) * PITCH + kc + (mat & 1) * 8) * 2;
                ldsm4(&bh[h16 * 4], a);
                ldsm4(&bl[h16 * 4], a + 5120);
            }
#pragma unroll
            for (int mt = 0; mt < 2; mt++)
#pragma unroll
                for (int nt = 0; nt < 4; nt++) {
                    mma16816(accU[mt][nt], ah[mt], &bh[nt * 2]);
                    mma16816(accU[mt][nt], ah[mt], &bl[nt * 2]);
                    mma16816(accU[mt][nt], al[mt], &bh[nt * 2]);
                }
        }
    };

    float4 vB[4];
    issueA(0, 0);
    loadB(0, vB);
    storeB(0, vB);
    cp_commit();
    cp_waitall();
    __syncthreads();

    const int C = DDIM / 32;  // 64
    for (int c = 0; c < C; c++) {
        int buf = c & 1;
        if (c + 1 < C) { issueA((c + 1) * 32, buf ^ 1); loadB((c + 1) * 32, vB); }
        compute(buf);
        if (c + 1 < C) {
            storeB(buf ^ 1, vB);
            cp_commit();
            cp_waitall();
            __syncthreads();
        }
    }

    int hbase = g_off[e];
#pragma unroll
    for (int mt = 0; mt < 2; mt++)
#pragma unroll
        for (int nt = 0; nt < 4; nt++) {
            int rb = m0 + mt * 16 + (lane >> 2);
            int col = f0 + n0 + nt * 8 + 2 * (lane & 3);
#pragma unroll
            for (int h = 0; h < 2; h++) {
                int r = rb + h * 8;
                if (r0 + r < n) {
                    float g0 = accG[mt][nt][2*h],   g1 = accG[mt][nt][2*h+1];
                    float u0 = accU[mt][nt][2*h],   u1 = accU[mt][nt][2*h+1];
                    float h0 = g0 * u0 / (1.f + __expf(-g0));
                    float h1 = g1 * u1 / (1.f + __expf(-g1));
                    __half a = __float2half_rn(h0), b = __float2half_rn(h1);
                    __half ra = __float2half_rn(h0 - __half2float(a));
                    __half rb2 = __float2half_rn(h1 - __half2float(b));
                    size_t ix = (size_t)(hbase + r0 + r) * FDIM + col;
                    *(uint32_t*)(g_hh + ix) = pack2h(a, b);
                    *(uint32_t*)(g_hl + ix) = pack2h(ra, rb2);
                }
            }
        }
}

// ---------------- down HMMA kernel ------------------------------------------
// stage layout (bytes): Ah 0 | Al 10240 | Bh 20480 | Bl 25600
#define DN_ST 30720
#define DN_DYN (2*DN_ST)

__global__ __launch_bounds__(256)
void down_mma(const float* __restrict__ wd) {
    int e = blockIdx.z;
    int n = g_cnt[e];
    int r0 = blockIdx.y * 128;
    if (r0 >= n) return;
    int d0 = blockIdx.x * 64;

    int tid = threadIdx.x, lane = tid & 31, wid = tid >> 5;
    uint32_t smb = s2u(dynsm);
    int hbase = g_off[e];

    int arow = tid & 127, aseg = tid >> 7;
    int brow = tid & 63, bhalf = (tid >> 6) & 1;
    const float* bptr0 = wd + ((size_t)e * DDIM + d0 + brow) * FDIM + bhalf * 16;
    bool bIsLo = (tid >= 128);  // threads 128-255 mirror rows for 2nd half of B? no:
    // B tile is 64 rows; 256 threads -> threads 0-127 load hi halves (16 floats each
    // covering rows 0-63 x k-halves 0-1); threads 128-255 duplicate rows with other
    // k-half? Instead: threads 0-127 load k0..15/k16..31 of rows 0..63 (full tile),
    // threads 128-255 idle on B. Keep it simple.
    bool bAct = (tid < 128);
    int bofs = 20480 + (brow * PITCH + bhalf * 16) * 2;

    auto issueA = [&](int k0, int st) {
        int r = r0 + arow;
        bool v = r < n;
        uint32_t d = smb + st * DN_ST + (arow * PITCH + aseg * 16) * 2;
        const __half* sh = g_hh + ((size_t)(hbase + (v ? r : 0)) * FDIM + k0 + aseg * 16);
        const __half* sl = g_hl + ((size_t)(hbase + (v ? r : 0)) * FDIM + k0 + aseg * 16);
        int sz = v ? 16 : 0;
        cp16(d,           sh,     sz);
        cp16(d + 16,      sh + 8, sz);
        cp16(d + 10240,      sl,     sz);
        cp16(d + 10240 + 16, sl + 8, sz);
    };
    auto loadB = [&](int k0, float4* v) {
        if (!bAct) return;
        const float* p = bptr0 + k0;
        v[0] = ((const float4*)p)[0];
        v[1] = ((const float4*)p)[1];
        v[2] = ((const float4*)p)[2];
        v[3] = ((const float4*)p)[3];
    };
    auto storeB = [&](int st, float4* v) {
        if (!bAct) return;
        char* d = dynsm + st * DN_ST + bofs;
        uint4 h0, l0, h1, l1;
        split8(v[0], v[1], h0, l0);
        split8(v[2], v[3], h1, l1);
        *(uint4*)(d)             = h0;
        *(uint4*)(d + 16)        = h1;
        *(uint4*)(d + 5120)      = l0;
        *(uint4*)(d + 5120 + 16) = l1;
    };

    float acc[2][4][4];
#pragma unroll
    for (int mt = 0; mt < 2; mt++)
#pragma unroll
        for (int nt = 0; nt < 4; nt++)
#pragma unroll
            for (int j = 0; j < 4; j++) acc[mt][nt][j] = 0.f;

    int m0 = (wid & 3) * 32, n0 = (wid >> 2) * 32;
    int mat = lane >> 3, rowin = lane & 7;

    auto compute = [&](int st) {
        uint32_t base = smb + st * DN_ST;
#pragma unroll
        for (int s = 0; s < 2; s++) {
            int kc = s * 16;
            uint32_t ah[2][4], al[2][4];
#pragma unroll
            for (int mt = 0; mt < 2; mt++) {
                uint32_t a = base +
                    ((m0 + mt * 16 + (mat & 1) * 8 + rowin) * PITCH + kc + (mat >> 1) * 8) * 2;
                ldsm4(ah[mt], a);
                ldsm4(al[mt], a + 10240);
            }
            uint32_t bh[8], bl[8];
#pragma unroll
            for (int h16 = 0; h16 < 2; h16++) {
                uint32_t a = base + 20480 +
                    ((n0 + h16 * 16 + (mat >> 1) * 8 + rowin) * PITCH + kc + (mat & 1) * 8) * 2;
                ldsm4(&bh[h16 * 4], a);
                ldsm4(&bl[h16 * 4], a + 5120);
            }
#pragma unroll
            for (int mt = 0; mt < 2; mt++)
#pragma unroll
                for (int nt = 0; nt < 4; nt++) {
                    mma16816(acc[mt][nt], ah[mt], &bh[nt * 2]);
                    mma16816(acc[mt][nt], ah[mt], &bl[nt * 2]);
                    mma16816(acc[mt][nt], al[mt], &bh[nt * 2]);
                }
        }
    };

    float4 vB[4];
    issueA(0, 0);
    loadB(0, vB);
    storeB(0, vB);
    cp_commit();
    cp_waitall();
    __syncthreads();

    const int C = FDIM / 32;  // 32
    for (int c = 0; c < C; c++) {
        int buf = c & 1;
        if (c + 1 < C) { issueA((c + 1) * 32, buf ^ 1); loadB((c + 1) * 32, vB); }
        compute(buf);
        if (c + 1 < C) {
            storeB(buf ^ 1, vB);
            cp_commit();
            cp_waitall();
            __syncthreads();
        }
    }

#pragma unroll
    for (int mt = 0; mt < 2; mt++)
#pragma unroll
        for (int nt = 0; nt < 4; nt++) {
            int rb = m0 + mt * 16 + (lane >> 2);
            int col = d0 + n0 + nt * 8 + 2 * (lane & 3);
#pragma unroll
            for (int h = 0; h < 2; h++) {
                int r = rb + h * 8;
                if (r0 + r < n) {
                    float2 v = make_float2(acc[mt][nt][2*h], acc[mt][nt][2*h+1]);
                    *(float2*)(g_y + (size_t)(hbase + r0 + r) * DDIM + col) = v;
                }
            }
        }
}

// ---------------- weighted combine ------------------------------------------
__global__ void combine_kernel(float* __restrict__ out) {
    int t = blockIdx.x;
    int e1 = g_te[2*t], e2 = g_te[2*t+1];
    int s1 = g_off[e1] + g_tp[2*t];
    int s2 = g_off[e2] + g_tp[2*t+1];
    float w1 = g_tw[2*t], w2 = g_tw[2*t+1];
    const float4* a = (const float4*)(g_y + (size_t)s1 * DDIM);
    const float4* b = (const float4*)(g_y + (size_t)s2 * DDIM);
    float4* o = (float4*)(out + (size_t)t * DDIM);
    for (int i = threadIdx.x; i < DDIM / 4; i += blockDim.x) {
        float4 av = a[i], bv = b[i];
        o[i] = make_float4(w1*av.x + w2*bv.x, w1*av.y + w2*bv.y,
                           w1*av.z + w2*bv.z, w1*av.w + w2*bv.w);
    }
}

// ---------------- launch ----------------------------------------------------
extern "C" void kernel_launch(void* const* d_in, const int* in_sizes, int n_in,
                              void* d_out, int out_size) {
    const float* x  = (const float*)d_in[0];
    const float* gw = (const float*)d_in[1];
    const float* wg = (const float*)d_in[2];
    const float* wu = (const float*)d_in[3];
    const float* wd = (const float*)d_in[4];
    float* out = (float*)d_out;

    int T = in_sizes[0] / DDIM;
    int write_logits = (out_size >= T * DDIM + T * NEXP) ? 1 : 0;
    float* logits = out + (size_t)T * DDIM;

    static int smem_set = 0;
    if (!smem_set) {
        cudaFuncSetAttribute(gateup_mma, cudaFuncAttributeMaxDynamicSharedMemorySize, GU_DYN);
        cudaFuncSetAttribute(down_mma,   cudaFuncAttributeMaxDynamicSharedMemorySize, DN_DYN);
        smem_set = 1;
    }

    reset_kernel<<<1, 32>>>();
    presplit_kernel<<<(T * DDIM / 4 + 255) / 256, 256>>>(x, T * DDIM / 4);
    router_kernel<<<T, 256>>>(x, gw, logits, write_logits);
    prefix_kernel<<<1, 1>>>();

    int ytiles = (T + 127) / 128;
    dim3 gg(FDIM / 64, ytiles, NEXP);
    gateup_mma<<<gg, 256, GU_DYN>>>(wg, wu);

    dim3 gd(DDIM / 64, ytiles, NEXP);
    down_mma<<<gd, 256, DN_DYN>>>(wd);

    combine_kernel<<<T, 256>>>(out);
}

// round 5
// speedup vs baseline: 2.9430x; 1.3851x over previous
#include <cuda_runtime.h>
#include <cuda_fp16.h>
#include <math.h>
#include <stdint.h>

#define NEXP 8
#define DDIM 2048
#define FDIM 1024
#define MAXT 2048
#define MAXSLOT (2*MAXT)
#define PITCH 40   // halves per 32-k row (64B data + 16B pad)

// ---------------- device scratch --------------------------------------------
__device__ int   g_cnt[NEXP];
__device__ int   g_off[NEXP];
__device__ int   g_list[NEXP*MAXT];
__device__ int   g_te[2*MAXT];
__device__ int   g_tp[2*MAXT];
__device__ float g_tw[2*MAXT];
__device__ __half g_xh[(size_t)MAXT*DDIM];
__device__ __half g_hh[(size_t)MAXSLOT*FDIM];
__device__ float  g_y[(size_t)MAXSLOT*DDIM];

// ---------------- helpers ----------------------------------------------------
__device__ __forceinline__ uint32_t s2u(const void* p) {
    return (uint32_t)__cvta_generic_to_shared(p);
}
__device__ __forceinline__ void ldsm4(uint32_t* r, uint32_t a) {
    asm volatile("ldmatrix.sync.aligned.m8n8.x4.shared.b16 {%0,%1,%2,%3}, [%4];"
                 : "=r"(r[0]), "=r"(r[1]), "=r"(r[2]), "=r"(r[3]) : "r"(a));
}
__device__ __forceinline__ void mma16816(float* c, const uint32_t* a,
                                         const uint32_t* b) {
    asm volatile(
        "mma.sync.aligned.m16n8k16.row.col.f32.f16.f16.f32 "
        "{%0,%1,%2,%3}, {%4,%5,%6,%7}, {%8,%9}, {%0,%1,%2,%3};"
        : "+f"(c[0]), "+f"(c[1]), "+f"(c[2]), "+f"(c[3])
        : "r"(a[0]), "r"(a[1]), "r"(a[2]), "r"(a[3]), "r"(b[0]), "r"(b[1]));
}
__device__ __forceinline__ void cp16(uint32_t dst, const void* src, int sz) {
    asm volatile("cp.async.ca.shared.global [%0], [%1], 16, %2;"
                 :: "r"(dst), "l"(src), "r"(sz) : "memory");
}
__device__ __forceinline__ void cp_commit() {
    asm volatile("cp.async.commit_group;" ::: "memory");
}
__device__ __forceinline__ void cp_waitall() {
    asm volatile("cp.async.wait_group 0;" ::: "memory");
}
__device__ __forceinline__ uint32_t pack2h(__half a, __half b) {
    return ((uint32_t)__half_as_ushort(b) << 16) | __half_as_ushort(a);
}
// 8 fp32 -> 8 hi halves + 8 lo halves
__device__ __forceinline__ void split8(float4 v0, float4 v1, uint4& h, uint4& l) {
    float f[8] = {v0.x,v0.y,v0.z,v0.w,v1.x,v1.y,v1.z,v1.w};
    uint32_t hh[4], ll[4];
#pragma unroll
    for (int j = 0; j < 4; j++) {
        __half a = __float2half_rn(f[2*j]);
        __half b = __float2half_rn(f[2*j+1]);
        __half ra = __float2half_rn(f[2*j]   - __half2float(a));
        __half rb = __float2half_rn(f[2*j+1] - __half2float(b));
        hh[j] = pack2h(a, b);
        ll[j] = pack2h(ra, rb);
    }
    h = make_uint4(hh[0],hh[1],hh[2],hh[3]);
    l = make_uint4(ll[0],ll[1],ll[2],ll[3]);
}

// ---------------- small kernels ---------------------------------------------
__global__ void presplit_kernel(const float* __restrict__ x, int n4) {
    int i = blockIdx.x * blockDim.x + threadIdx.x;
    if (blockIdx.x == 0 && threadIdx.x < NEXP) g_cnt[threadIdx.x] = 0;
    if (i >= n4) return;
    float4 v = ((const float4*)x)[i];
    float f[4] = {v.x, v.y, v.z, v.w};
    ushort h[4];
#pragma unroll
    for (int j = 0; j < 4; j++) h[j] = __half_as_ushort(__float2half_rn(f[j]));
    ((uint2*)g_xh)[i] = make_uint2(((uint32_t)h[1]<<16)|h[0], ((uint32_t)h[3]<<16)|h[2]);
}

__global__ void router_kernel(const float* __restrict__ x,
                              const float* __restrict__ gw,
                              float* __restrict__ logits_out,
                              int write_logits) {
    __shared__ float xs[DDIM];
    __shared__ float lg[NEXP];
    int t = blockIdx.x;
    const float* xr = x + (size_t)t * DDIM;
    for (int i = threadIdx.x; i < DDIM; i += blockDim.x) xs[i] = xr[i];
    __syncthreads();

    int w = threadIdx.x >> 5, lane = threadIdx.x & 31;
    if (w < NEXP) {
        const float* g = gw + (size_t)w * DDIM;
        float s = 0.f;
        for (int d = lane; d < DDIM; d += 32) s = fmaf(xs[d], g[d], s);
        for (int o = 16; o; o >>= 1) s += __shfl_xor_sync(0xffffffffu, s, o);
        if (lane == 0) lg[w] = s;
    }
    __syncthreads();

    if (threadIdx.x == 0) {
        float l[NEXP], p[NEXP];
        float m = -1e30f;
        for (int e = 0; e < NEXP; e++) {
            l[e] = lg[e];
            if (write_logits) logits_out[(size_t)t * NEXP + e] = l[e];
            m = fmaxf(m, l[e]);
        }
        float se = 0.f;
        for (int e = 0; e < NEXP; e++) { p[e] = expf(l[e] - m); se += p[e]; }
        float inv = 1.f / se;
        for (int e = 0; e < NEXP; e++) p[e] *= inv;
        int i1 = 0;
        for (int e = 1; e < NEXP; e++) if (p[e] > p[i1]) i1 = e;
        int i2 = -1;
        for (int e = 0; e < NEXP; e++) {
            if (e == i1) continue;
            if (i2 < 0 || p[e] > p[i2]) i2 = e;
        }
        float s12 = p[i1] + p[i2];
        float w1 = p[i1] / s12, w2 = p[i2] / s12;
        int p1 = atomicAdd(&g_cnt[i1], 1);
        g_list[i1 * MAXT + p1] = t;
        int p2 = atomicAdd(&g_cnt[i2], 1);
        g_list[i2 * MAXT + p2] = t;
        g_te[2*t] = i1;   g_tp[2*t] = p1;   g_tw[2*t] = w1;
        g_te[2*t+1] = i2; g_tp[2*t+1] = p2; g_tw[2*t+1] = w2;
    }
}

__global__ void prefix_kernel() {
    int o = 0;
    for (int e = 0; e < NEXP; e++) { g_off[e] = o; o += g_cnt[e]; }
}

extern __shared__ __align__(16) char dynsm[];

// ---------------- gate+up HMMA kernel ---------------------------------------
// stage layout (bytes): Ah 0 | Gh 10240 | Gl 15360 | Uh 20480 | Ul 25600
#define GU_ST 30720
#define GU_DYN (2*GU_ST)

__global__ __launch_bounds__(256)
void gateup_mma(const float* __restrict__ wg, const float* __restrict__ wu) {
    int e = blockIdx.z;
    int n = g_cnt[e];
    int r0 = blockIdx.y * 128;
    if (r0 >= n) return;
    int f0 = blockIdx.x * 64;

    __shared__ int toks[128];
    int tid = threadIdx.x, lane = tid & 31, wid = tid >> 5;
    uint32_t smb = s2u(dynsm);

    if (tid < 128) {
        int r = r0 + tid;
        toks[tid] = (r < n) ? g_list[e * MAXT + r] : -1;
    }
    __syncthreads();

    const float* wge = wg + (size_t)e * FDIM * DDIM + (size_t)f0 * DDIM;
    const float* wue = wu + (size_t)e * FDIM * DDIM + (size_t)f0 * DDIM;

    int arow = tid & 127, aseg = tid >> 7;          // A loader mapping
    int brow = tid & 63, bhalf = (tid >> 6) & 1;    // B loader mapping
    const float* bptr = (tid >= 128 ? wue : wge) + (size_t)brow * DDIM + bhalf * 16;
    int bofs = (tid >= 128 ? 20480 : 10240) + (brow * PITCH + bhalf * 16) * 2;

    auto issueA = [&](int k0, int st) {
        int tk = toks[arow];
        uint32_t d = smb + st * GU_ST + (arow * PITCH + aseg * 16) * 2;
        const __half* sh = g_xh + ((size_t)(tk < 0 ? 0 : tk) * DDIM + k0 + aseg * 16);
        int sz = (tk < 0) ? 0 : 16;
        cp16(d,      sh,     sz);
        cp16(d + 16, sh + 8, sz);
    };
    auto loadB = [&](int k0, float4* v) {
        const float* p = bptr + k0;
        v[0] = ((const float4*)p)[0];
        v[1] = ((const float4*)p)[1];
        v[2] = ((const float4*)p)[2];
        v[3] = ((const float4*)p)[3];
    };
    auto storeB = [&](int st, float4* v) {
        char* d = dynsm + st * GU_ST + bofs;
        uint4 h0, l0, h1, l1;
        split8(v[0], v[1], h0, l0);
        split8(v[2], v[3], h1, l1);
        *(uint4*)(d)             = h0;
        *(uint4*)(d + 16)        = h1;
        *(uint4*)(d + 5120)      = l0;
        *(uint4*)(d + 5120 + 16) = l1;
    };

    float accG[2][4][4], accU[2][4][4];
#pragma unroll
    for (int mt = 0; mt < 2; mt++)
#pragma unroll
        for (int nt = 0; nt < 4; nt++)
#pragma unroll
            for (int j = 0; j < 4; j++) { accG[mt][nt][j] = 0.f; accU[mt][nt][j] = 0.f; }

    int m0 = (wid & 3) * 32, n0 = (wid >> 2) * 32;
    int mat = lane >> 3, rowin = lane & 7;

    auto compute = [&](int st) {
        uint32_t base = smb + st * GU_ST;
#pragma unroll
        for (int s = 0; s < 2; s++) {
            int kc = s * 16;
            uint32_t ah[2][4];
#pragma unroll
            for (int mt = 0; mt < 2; mt++) {
                uint32_t a = base +
                    ((m0 + mt * 16 + (mat & 1) * 8 + rowin) * PITCH + kc + (mat >> 1) * 8) * 2;
                ldsm4(ah[mt], a);
            }
            uint32_t bh[8], bl[8];
#pragma unroll
            for (int h16 = 0; h16 < 2; h16++) {
                uint32_t a = base + 10240 +
                    ((n0 + h16 * 16 + (mat >> 1) * 8 + rowin) * PITCH + kc + (mat & 1) * 8) * 2;
                ldsm4(&bh[h16 * 4], a);
                ldsm4(&bl[h16 * 4], a + 5120);
            }
#pragma unroll
            for (int mt = 0; mt < 2; mt++)
#pragma unroll
                for (int nt = 0; nt < 4; nt++) {
                    mma16816(accG[mt][nt], ah[mt], &bh[nt * 2]);
                    mma16816(accG[mt][nt], ah[mt], &bl[nt * 2]);
                }
#pragma unroll
            for (int h16 = 0; h16 < 2; h16++) {
                uint32_t a = base + 20480 +
                    ((n0 + h16 * 16 + (mat >> 1) * 8 + rowin) * PITCH + kc + (mat & 1) * 8) * 2;
                ldsm4(&bh[h16 * 4], a);
                ldsm4(&bl[h16 * 4], a + 5120);
            }
#pragma unroll
            for (int mt = 0; mt < 2; mt++)
#pragma unroll
                for (int nt = 0; nt < 4; nt++) {
                    mma16816(accU[mt][nt], ah[mt], &bh[nt * 2]);
                    mma16816(accU[mt][nt], ah[mt], &bl[nt * 2]);
                }
        }
    };

    float4 vB[4];
    issueA(0, 0);
    loadB(0, vB);
    storeB(0, vB);
    cp_commit();
    cp_waitall();
    __syncthreads();

    const int C = DDIM / 32;  // 64
    for (int c = 0; c < C; c++) {
        int buf = c & 1;
        if (c + 1 < C) { issueA((c + 1) * 32, buf ^ 1); loadB((c + 1) * 32, vB); }
        compute(buf);
        if (c + 1 < C) {
            storeB(buf ^ 1, vB);
            cp_commit();
            cp_waitall();
            __syncthreads();
        }
    }

    int hbase = g_off[e];
#pragma unroll
    for (int mt = 0; mt < 2; mt++)
#pragma unroll
        for (int nt = 0; nt < 4; nt++) {
            int rb = m0 + mt * 16 + (lane >> 2);
            int col = f0 + n0 + nt * 8 + 2 * (lane & 3);
#pragma unroll
            for (int h = 0; h < 2; h++) {
                int r = rb + h * 8;
                if (r0 + r < n) {
                    float g0 = accG[mt][nt][2*h],   g1 = accG[mt][nt][2*h+1];
                    float u0 = accU[mt][nt][2*h],   u1 = accU[mt][nt][2*h+1];
                    float h0 = g0 * u0 / (1.f + __expf(-g0));
                    float h1 = g1 * u1 / (1.f + __expf(-g1));
                    size_t ix = (size_t)(hbase + r0 + r) * FDIM + col;
                    *(uint32_t*)(g_hh + ix) =
                        pack2h(__float2half_rn(h0), __float2half_rn(h1));
                }
            }
        }
}

// ---------------- down HMMA kernel ------------------------------------------
// stage layout (bytes): Ah 0 | Bh 10240 | Bl 15360
#define DN_ST 20480
#define DN_DYN (2*DN_ST)

__global__ __launch_bounds__(256)
void down_mma(const float* __restrict__ wd) {
    int e = blockIdx.z;
    int n = g_cnt[e];
    int r0 = blockIdx.y * 128;
    if (r0 >= n) return;
    int d0 = blockIdx.x * 64;

    int tid = threadIdx.x, lane = tid & 31, wid = tid >> 5;
    uint32_t smb = s2u(dynsm);
    int hbase = g_off[e];

    int arow = tid & 127, aseg = tid >> 7;
    int brow = tid & 63, bhalf = (tid >> 6) & 1;
    const float* bptr0 = wd + ((size_t)e * DDIM + d0 + brow) * FDIM + bhalf * 16;
    bool bAct = (tid < 128);
    int bofs = 10240 + (brow * PITCH + bhalf * 16) * 2;

    auto issueA = [&](int k0, int st) {
        int r = r0 + arow;
        bool v = r < n;
        uint32_t d = smb + st * DN_ST + (arow * PITCH + aseg * 16) * 2;
        const __half* sh = g_hh + ((size_t)(hbase + (v ? r : 0)) * FDIM + k0 + aseg * 16);
        int sz = v ? 16 : 0;
        cp16(d,      sh,     sz);
        cp16(d + 16, sh + 8, sz);
    };
    auto loadB = [&](int k0, float4* v) {
        if (!bAct) return;
        const float* p = bptr0 + k0;
        v[0] = ((const float4*)p)[0];
        v[1] = ((const float4*)p)[1];
        v[2] = ((const float4*)p)[2];
        v[3] = ((const float4*)p)[3];
    };
    auto storeB = [&](int st, float4* v) {
        if (!bAct) return;
        char* d = dynsm + st * DN_ST + bofs;
        uint4 h0, l0, h1, l1;
        split8(v[0], v[1], h0, l0);
        split8(v[2], v[3], h1, l1);
        *(uint4*)(d)             = h0;
        *(uint4*)(d + 16)        = h1;
        *(uint4*)(d + 5120)      = l0;
        *(uint4*)(d + 5120 + 16) = l1;
    };

    float acc[2][4][4];
#pragma unroll
    for (int mt = 0; mt < 2; mt++)
#pragma unroll
        for (int nt = 0; nt < 4; nt++)
#pragma unroll
            for (int j = 0; j < 4; j++) acc[mt][nt][j] = 0.f;

    int m0 = (wid & 3) * 32, n0 = (wid >> 2) * 32;
    int mat = lane >> 3, rowin = lane & 7;

    auto compute = [&](int st) {
        uint32_t base = smb + st * DN_ST;
#pragma unroll
        for (int s = 0; s < 2; s++) {
            int kc = s * 16;
            uint32_t ah[2][4];
#pragma unroll
            for (int mt = 0; mt < 2; mt++) {
                uint32_t a = base +
                    ((m0 + mt * 16 + (mat & 1) * 8 + rowin) * PITCH + kc + (mat >> 1) * 8) * 2;
                ldsm4(ah[mt], a);
            }
            uint32_t bh[8], bl[8];
#pragma unroll
            for (int h16 = 0; h16 < 2; h16++) {
                uint32_t a = base + 10240 +
                    ((n0 + h16 * 16 + (mat >> 1) * 8 + rowin) * PITCH + kc + (mat & 1) * 8) * 2;
                ldsm4(&bh[h16 * 4], a);
                ldsm4(&bl[h16 * 4], a + 5120);
            }
#pragma unroll
            for (int mt = 0; mt < 2; mt++)
#pragma unroll
                for (int nt = 0; nt < 4; nt++) {
                    mma16816(acc[mt][nt], ah[mt], &bh[nt * 2]);
                    mma16816(acc[mt][nt], ah[mt], &bl[nt * 2]);
                }
        }
    };

    float4 vB[4];
    issueA(0, 0);
    loadB(0, vB);
    storeB(0, vB);
    cp_commit();
    cp_waitall();
    __syncthreads();

    const int C = FDIM / 32;  // 32
    for (int c = 0; c < C; c++) {
        int buf = c & 1;
        if (c + 1 < C) { issueA((c + 1) * 32, buf ^ 1); loadB((c + 1) * 32, vB); }
        compute(buf);
        if (c + 1 < C) {
            storeB(buf ^ 1, vB);
            cp_commit();
            cp_waitall();
            __syncthreads();
        }
    }

#pragma unroll
    for (int mt = 0; mt < 2; mt++)
#pragma unroll
        for (int nt = 0; nt < 4; nt++) {
            int rb = m0 + mt * 16 + (lane >> 2);
            int col = d0 + n0 + nt * 8 + 2 * (lane & 3);
#pragma unroll
            for (int h = 0; h < 2; h++) {
                int r = rb + h * 8;
                if (r0 + r < n) {
                    float2 v = make_float2(acc[mt][nt][2*h], acc[mt][nt][2*h+1]);
                    *(float2*)(g_y + (size_t)(hbase + r0 + r) * DDIM + col) = v;
                }
            }
        }
}

// ---------------- weighted combine ------------------------------------------
__global__ void combine_kernel(float* __restrict__ out) {
    int t = blockIdx.x;
    int e1 = g_te[2*t], e2 = g_te[2*t+1];
    int s1 = g_off[e1] + g_tp[2*t];
    int s2 = g_off[e2] + g_tp[2*t+1];
    float w1 = g_tw[2*t], w2 = g_tw[2*t+1];
    const float4* a = (const float4*)(g_y + (size_t)s1 * DDIM);
    const float4* b = (const float4*)(g_y + (size_t)s2 * DDIM);
    float4* o = (float4*)(out + (size_t)t * DDIM);
    for (int i = threadIdx.x; i < DDIM / 4; i += blockDim.x) {
        float4 av = a[i], bv = b[i];
        o[i] = make_float4(w1*av.x + w2*bv.x, w1*av.y + w2*bv.y,
                           w1*av.z + w2*bv.z, w1*av.w + w2*bv.w);
    }
}

// ---------------- launch ----------------------------------------------------
extern "C" void kernel_launch(void* const* d_in, const int* in_sizes, int n_in,
                              void* d_out, int out_size) {
    const float* x  = (const float*)d_in[0];
    const float* gw = (const float*)d_in[1];
    const float* wg = (const float*)d_in[2];
    const float* wu = (const float*)d_in[3];
    const float* wd = (const float*)d_in[4];
    float* out = (float*)d_out;

    int T = in_sizes[0] / DDIM;
    int write_logits = (out_size >= T * DDIM + T * NEXP) ? 1 : 0;
    float* logits = out + (size_t)T * DDIM;

    static int smem_set = 0;
    if (!smem_set) {
        cudaFuncSetAttribute(gateup_mma, cudaFuncAttributeMaxDynamicSharedMemorySize, GU_DYN);
        cudaFuncSetAttribute(down_mma,   cudaFuncAttributeMaxDynamicSharedMemorySize, DN_DYN);
        smem_set = 1;
    }

    presplit_kernel<<<(T * DDIM / 4 + 255) / 256, 256>>>(x, T * DDIM / 4);
    router_kernel<<<T, 256>>>(x, gw, logits, write_logits);
    prefix_kernel<<<1, 1>>>();

    int ytiles = (T + 127) / 128;
    dim3 gg(FDIM / 64, ytiles, NEXP);
    gateup_mma<<<gg, 256, GU_DYN>>>(wg, wu);

    dim3 gd(DDIM / 64, ytiles, NEXP);
    down_mma<<<gd, 256, DN_DYN>>>(wd);

    combine_kernel<<<T, 256>>>(out);
}

// round 6
// speedup vs baseline: 3.4523x; 1.1730x over previous
#include <cuda_runtime.h>
#include <cuda_fp16.h>
#include <math.h>
#include <stdint.h>

#define NEXP 8
#define DDIM 2048
#define FDIM 1024
#define MAXT 2048
#define MAXSLOT (2*MAXT)
#define PITCH 40   // halves per 32-k row (64B data + 16B pad)

// ---------------- device scratch --------------------------------------------
__device__ int   g_cnt[NEXP];
__device__ int   g_off[NEXP];
__device__ int   g_list[NEXP*MAXT];
__device__ int   g_te[2*MAXT];
__device__ int   g_tp[2*MAXT];
__device__ float g_tw[2*MAXT];
__device__ __half g_xh[(size_t)MAXT*DDIM];
__device__ __half g_hh[(size_t)MAXSLOT*FDIM];
__device__ float  g_y[(size_t)MAXSLOT*DDIM];

// ---------------- helpers ----------------------------------------------------
__device__ __forceinline__ uint32_t s2u(const void* p) {
    return (uint32_t)__cvta_generic_to_shared(p);
}
__device__ __forceinline__ void ldsm4(uint32_t* r, uint32_t a) {
    asm volatile("ldmatrix.sync.aligned.m8n8.x4.shared.b16 {%0,%1,%2,%3}, [%4];"
                 : "=r"(r[0]), "=r"(r[1]), "=r"(r[2]), "=r"(r[3]) : "r"(a));
}
__device__ __forceinline__ void mma16816(float* c, const uint32_t* a,
                                         const uint32_t* b) {
    asm volatile(
        "mma.sync.aligned.m16n8k16.row.col.f32.f16.f16.f32 "
        "{%0,%1,%2,%3}, {%4,%5,%6,%7}, {%8,%9}, {%0,%1,%2,%3};"
        : "+f"(c[0]), "+f"(c[1]), "+f"(c[2]), "+f"(c[3])
        : "r"(a[0]), "r"(a[1]), "r"(a[2]), "r"(a[3]), "r"(b[0]), "r"(b[1]));
}
__device__ __forceinline__ void cp16(uint32_t dst, const void* src, int sz) {
    asm volatile("cp.async.ca.shared.global [%0], [%1], 16, %2;"
                 :: "r"(dst), "l"(src), "r"(sz) : "memory");
}
__device__ __forceinline__ void cp_commit() {
    asm volatile("cp.async.commit_group;" ::: "memory");
}
__device__ __forceinline__ void cp_waitall() {
    asm volatile("cp.async.wait_group 0;" ::: "memory");
}
__device__ __forceinline__ uint32_t pack2h(__half a, __half b) {
    return ((uint32_t)__half_as_ushort(b) << 16) | __half_as_ushort(a);
}
// 8 fp32 -> 8 hi halves + 8 lo halves
__device__ __forceinline__ void split8(float4 v0, float4 v1, uint4& h, uint4& l) {
    float f[8] = {v0.x,v0.y,v0.z,v0.w,v1.x,v1.y,v1.z,v1.w};
    uint32_t hh[4], ll[4];
#pragma unroll
    for (int j = 0; j < 4; j++) {
        __half a = __float2half_rn(f[2*j]);
        __half b = __float2half_rn(f[2*j+1]);
        __half ra = __float2half_rn(f[2*j]   - __half2float(a));
        __half rb = __float2half_rn(f[2*j+1] - __half2float(b));
        hh[j] = pack2h(a, b);
        ll[j] = pack2h(ra, rb);
    }
    h = make_uint4(hh[0],hh[1],hh[2],hh[3]);
    l = make_uint4(ll[0],ll[1],ll[2],ll[3]);
}

// ---------------- small kernels ---------------------------------------------
__global__ void presplit_kernel(const float* __restrict__ x, int n4) {
    int i = blockIdx.x * blockDim.x + threadIdx.x;
    if (blockIdx.x == 0 && threadIdx.x < NEXP) g_cnt[threadIdx.x] = 0;
    if (i >= n4) return;
    float4 v = ((const float4*)x)[i];
    float f[4] = {v.x, v.y, v.z, v.w};
    ushort h[4];
#pragma unroll
    for (int j = 0; j < 4; j++) h[j] = __half_as_ushort(__float2half_rn(f[j]));
    ((uint2*)g_xh)[i] = make_uint2(((uint32_t)h[1]<<16)|h[0], ((uint32_t)h[3]<<16)|h[2]);
}

__global__ void router_kernel(const float* __restrict__ x,
                              const float* __restrict__ gw,
                              float* __restrict__ logits_out,
                              int write_logits) {
    __shared__ float xs[DDIM];
    __shared__ float lg[NEXP];
    int t = blockIdx.x;
    const float* xr = x + (size_t)t * DDIM;
    for (int i = threadIdx.x; i < DDIM; i += blockDim.x) xs[i] = xr[i];
    __syncthreads();

    int w = threadIdx.x >> 5, lane = threadIdx.x & 31;
    if (w < NEXP) {
        const float* g = gw + (size_t)w * DDIM;
        float s = 0.f;
        for (int d = lane; d < DDIM; d += 32) s = fmaf(xs[d], g[d], s);
        for (int o = 16; o; o >>= 1) s += __shfl_xor_sync(0xffffffffu, s, o);
        if (lane == 0) lg[w] = s;
    }
    __syncthreads();

    if (threadIdx.x == 0) {
        float l[NEXP], p[NEXP];
        float m = -1e30f;
        for (int e = 0; e < NEXP; e++) {
            l[e] = lg[e];
            if (write_logits) logits_out[(size_t)t * NEXP + e] = l[e];
            m = fmaxf(m, l[e]);
        }
        float se = 0.f;
        for (int e = 0; e < NEXP; e++) { p[e] = expf(l[e] - m); se += p[e]; }
        float inv = 1.f / se;
        for (int e = 0; e < NEXP; e++) p[e] *= inv;
        int i1 = 0;
        for (int e = 1; e < NEXP; e++) if (p[e] > p[i1]) i1 = e;
        int i2 = -1;
        for (int e = 0; e < NEXP; e++) {
            if (e == i1) continue;
            if (i2 < 0 || p[e] > p[i2]) i2 = e;
        }
        float s12 = p[i1] + p[i2];
        float w1 = p[i1] / s12, w2 = p[i2] / s12;
        int p1 = atomicAdd(&g_cnt[i1], 1);
        g_list[i1 * MAXT + p1] = t;
        int p2 = atomicAdd(&g_cnt[i2], 1);
        g_list[i2 * MAXT + p2] = t;
        g_te[2*t] = i1;   g_tp[2*t] = p1;   g_tw[2*t] = w1;
        g_te[2*t+1] = i2; g_tp[2*t+1] = p2; g_tw[2*t+1] = w2;
    }
}

__global__ void prefix_kernel() {
    int o = 0;
    for (int e = 0; e < NEXP; e++) { g_off[e] = o; o += g_cnt[e]; }
}

extern __shared__ __align__(16) char dynsm[];

// ---------------- gate+up HMMA kernel ---------------------------------------
// CTA tile: 128 slots x 128 f-cols (gate AND up). warps 2(m) x 4(n), warp 64x32.
// stage layout (bytes): A 0 | GH 10240 | GL 20480 | UH 30720 | UL 40960
#define GU_ST 51200
#define GU_DYN (2*GU_ST)

__global__ __launch_bounds__(256)
void gateup_mma(const float* __restrict__ wg, const float* __restrict__ wu) {
    int e = blockIdx.z;
    int n = g_cnt[e];
    int r0 = blockIdx.y * 128;
    if (r0 >= n) return;
    int f0 = blockIdx.x * 128;

    __shared__ int toks[128];
    int tid = threadIdx.x, lane = tid & 31, wid = tid >> 5;
    uint32_t smb = s2u(dynsm);

    if (tid < 128) {
        int r = r0 + tid;
        toks[tid] = (r < n) ? g_list[e * MAXT + r] : -1;
    }
    __syncthreads();

    const float* wge = wg + (size_t)e * FDIM * DDIM + (size_t)f0 * DDIM;
    const float* wue = wu + (size_t)e * FDIM * DDIM + (size_t)f0 * DDIM;

    int arow = tid & 127, aseg = tid >> 7;          // A loader
    int brow = tid & 127;                            // B loader: row in section
    const float* bsrc = (tid < 128) ? (wge + (size_t)brow * DDIM)
                                    : (wue + (size_t)brow * DDIM);
    int bsec = (tid < 128) ? 10240 : 30720;          // hi section; lo = +10240
    int bro = brow * PITCH * 2;

    auto issueA = [&](int k0, int st) {
        int tk = toks[arow];
        uint32_t d = smb + st * GU_ST + (arow * PITCH + aseg * 16) * 2;
        const __half* sh = g_xh + ((size_t)(tk < 0 ? 0 : tk) * DDIM + k0 + aseg * 16);
        int sz = (tk < 0) ? 0 : 16;
        cp16(d,      sh,     sz);
        cp16(d + 16, sh + 8, sz);
    };
    float4 vB[4];
    auto loadB = [&](int k0, int h) {
        const float* p = bsrc + k0 + h * 16;
        vB[0] = ((const float4*)p)[0];
        vB[1] = ((const float4*)p)[1];
        vB[2] = ((const float4*)p)[2];
        vB[3] = ((const float4*)p)[3];
    };
    auto storeB = [&](int st, int h) {
        char* d = dynsm + st * GU_ST + bsec + bro + h * 32;
        uint4 h0, l0, h1, l1;
        split8(vB[0], vB[1], h0, l0);
        split8(vB[2], vB[3], h1, l1);
        *(uint4*)(d)              = h0;
        *(uint4*)(d + 16)         = h1;
        *(uint4*)(d + 10240)      = l0;
        *(uint4*)(d + 10240 + 16) = l1;
    };

    float accG[4][4][4], accU[4][4][4];
#pragma unroll
    for (int mt = 0; mt < 4; mt++)
#pragma unroll
        for (int nt = 0; nt < 4; nt++)
#pragma unroll
            for (int j = 0; j < 4; j++) { accG[mt][nt][j] = 0.f; accU[mt][nt][j] = 0.f; }

    int m0 = (wid & 1) * 64, n0 = (wid >> 1) * 32;
    int mat = lane >> 3, rowin = lane & 7;

    auto compute_slab = [&](int st, int s) {
        uint32_t base = smb + st * GU_ST;
        int kc = s * 16;
        uint32_t ah[4][4];
#pragma unroll
        for (int mt = 0; mt < 4; mt++) {
            uint32_t a = base +
                ((m0 + mt * 16 + (mat & 1) * 8 + rowin) * PITCH + kc + (mat >> 1) * 8) * 2;
            ldsm4(ah[mt], a);
        }
        uint32_t bh[8], bl[8];
        // gate
#pragma unroll
        for (int h16 = 0; h16 < 2; h16++) {
            uint32_t a = base + 10240 +
                ((n0 + h16 * 16 + (mat >> 1) * 8 + rowin) * PITCH + kc + (mat & 1) * 8) * 2;
            ldsm4(&bh[h16 * 4], a);
            ldsm4(&bl[h16 * 4], a + 10240);
        }
#pragma unroll
        for (int mt = 0; mt < 4; mt++)
#pragma unroll
            for (int nt = 0; nt < 4; nt++) {
                mma16816(accG[mt][nt], ah[mt], &bh[nt * 2]);
                mma16816(accG[mt][nt], ah[mt], &bl[nt * 2]);
            }
        // up
#pragma unroll
        for (int h16 = 0; h16 < 2; h16++) {
            uint32_t a = base + 30720 +
                ((n0 + h16 * 16 + (mat >> 1) * 8 + rowin) * PITCH + kc + (mat & 1) * 8) * 2;
            ldsm4(&bh[h16 * 4], a);
            ldsm4(&bl[h16 * 4], a + 10240);
        }
#pragma unroll
        for (int mt = 0; mt < 4; mt++)
#pragma unroll
            for (int nt = 0; nt < 4; nt++) {
                mma16816(accU[mt][nt], ah[mt], &bh[nt * 2]);
                mma16816(accU[mt][nt], ah[mt], &bl[nt * 2]);
            }
    };

    issueA(0, 0);
    loadB(0, 0); storeB(0, 0);
    loadB(0, 1); storeB(0, 1);
    cp_commit();
    cp_waitall();
    __syncthreads();

    const int C = DDIM / 32;  // 64
    for (int c = 0; c < C; c++) {
        int buf = c & 1;
        if (c + 1 < C) { issueA((c + 1) * 32, buf ^ 1); loadB((c + 1) * 32, 0); }
        compute_slab(buf, 0);
        if (c + 1 < C) { storeB(buf ^ 1, 0); loadB((c + 1) * 32, 1); }
        compute_slab(buf, 1);
        if (c + 1 < C) {
            storeB(buf ^ 1, 1);
            cp_commit();
            cp_waitall();
            __syncthreads();
        }
    }

    int hbase = g_off[e];
#pragma unroll
    for (int mt = 0; mt < 4; mt++)
#pragma unroll
        for (int nt = 0; nt < 4; nt++) {
            int rb = m0 + mt * 16 + (lane >> 2);
            int col = f0 + n0 + nt * 8 + 2 * (lane & 3);
#pragma unroll
            for (int h = 0; h < 2; h++) {
                int r = rb + h * 8;
                if (r0 + r < n) {
                    float g0 = accG[mt][nt][2*h],   g1 = accG[mt][nt][2*h+1];
                    float u0 = accU[mt][nt][2*h],   u1 = accU[mt][nt][2*h+1];
                    float h0 = g0 * u0 / (1.f + __expf(-g0));
                    float h1 = g1 * u1 / (1.f + __expf(-g1));
                    size_t ix = (size_t)(hbase + r0 + r) * FDIM + col;
                    *(uint32_t*)(g_hh + ix) =
                        pack2h(__float2half_rn(h0), __float2half_rn(h1));
                }
            }
        }
}

// ---------------- down HMMA kernel ------------------------------------------
// CTA tile: 128 slots x 128 d-cols. warps 2(m) x 4(n), warp 64x32.
// stage layout (bytes): A 0 | BH 10240 | BL 20480
#define DN_ST 30720
#define DN_DYN (2*DN_ST)

__global__ __launch_bounds__(256)
void down_mma(const float* __restrict__ wd) {
    int e = blockIdx.z;
    int n = g_cnt[e];
    int r0 = blockIdx.y * 128;
    if (r0 >= n) return;
    int d0 = blockIdx.x * 128;

    int tid = threadIdx.x, lane = tid & 31, wid = tid >> 5;
    uint32_t smb = s2u(dynsm);
    int hbase = g_off[e];

    int arow = tid & 127, aseg = tid >> 7;
    int brow = tid & 127, bhalf = tid >> 7;
    const float* bsrc = wd + ((size_t)e * DDIM + d0 + brow) * FDIM + bhalf * 16;
    int bro = (brow * PITCH + bhalf * 16) * 2;

    auto issueA = [&](int k0, int st) {
        int r = r0 + arow;
        bool v = r < n;
        uint32_t d = smb + st * DN_ST + (arow * PITCH + aseg * 16) * 2;
        const __half* sh = g_hh + ((size_t)(hbase + (v ? r : 0)) * FDIM + k0 + aseg * 16);
        int sz = v ? 16 : 0;
        cp16(d,      sh,     sz);
        cp16(d + 16, sh + 8, sz);
    };
    float4 vB[4];
    auto loadB = [&](int k0) {
        const float* p = bsrc + k0;
        vB[0] = ((const float4*)p)[0];
        vB[1] = ((const float4*)p)[1];
        vB[2] = ((const float4*)p)[2];
        vB[3] = ((const float4*)p)[3];
    };
    auto storeB = [&](int st) {
        char* d = dynsm + st * DN_ST + 10240 + bro;
        uint4 h0, l0, h1, l1;
        split8(vB[0], vB[1], h0, l0);
        split8(vB[2], vB[3], h1, l1);
        *(uint4*)(d)              = h0;
        *(uint4*)(d + 16)         = h1;
        *(uint4*)(d + 10240)      = l0;
        *(uint4*)(d + 10240 + 16) = l1;
    };

    float acc[4][4][4];
#pragma unroll
    for (int mt = 0; mt < 4; mt++)
#pragma unroll
        for (int nt = 0; nt < 4; nt++)
#pragma unroll
            for (int j = 0; j < 4; j++) acc[mt][nt][j] = 0.f;

    int m0 = (wid & 1) * 64, n0 = (wid >> 1) * 32;
    int mat = lane >> 3, rowin = lane & 7;

    auto compute_slab = [&](int st, int s) {
        uint32_t base = smb + st * DN_ST;
        int kc = s * 16;
        uint32_t ah[4][4];
#pragma unroll
        for (int mt = 0; mt < 4; mt++) {
            uint32_t a = base +
                ((m0 + mt * 16 + (mat & 1) * 8 + rowin) * PITCH + kc + (mat >> 1) * 8) * 2;
            ldsm4(ah[mt], a);
        }
        uint32_t bh[8], bl[8];
#pragma unroll
        for (int h16 = 0; h16 < 2; h16++) {
            uint32_t a = base + 10240 +
                ((n0 + h16 * 16 + (mat >> 1) * 8 + rowin) * PITCH + kc + (mat & 1) * 8) * 2;
            ldsm4(&bh[h16 * 4], a);
            ldsm4(&bl[h16 * 4], a + 10240);
        }
#pragma unroll
        for (int mt = 0; mt < 4; mt++)
#pragma unroll
            for (int nt = 0; nt < 4; nt++) {
                mma16816(acc[mt][nt], ah[mt], &bh[nt * 2]);
                mma16816(acc[mt][nt], ah[mt], &bl[nt * 2]);
            }
    };

    issueA(0, 0);
    loadB(0); storeB(0);
    cp_commit();
    cp_waitall();
    __syncthreads();

    const int C = FDIM / 32;  // 32
    for (int c = 0; c < C; c++) {
        int buf = c & 1;
        if (c + 1 < C) { issueA((c + 1) * 32, buf ^ 1); loadB((c + 1) * 32); }
        compute_slab(buf, 0);
        compute_slab(buf, 1);
        if (c + 1 < C) {
            storeB(buf ^ 1);
            cp_commit();
            cp_waitall();
            __syncthreads();
        }
    }

#pragma unroll
    for (int mt = 0; mt < 4; mt++)
#pragma unroll
        for (int nt = 0; nt < 4; nt++) {
            int rb = m0 + mt * 16 + (lane >> 2);
            int col = d0 + n0 + nt * 8 + 2 * (lane & 3);
#pragma unroll
            for (int h = 0; h < 2; h++) {
                int r = rb + h * 8;
                if (r0 + r < n) {
                    float2 v = make_float2(acc[mt][nt][2*h], acc[mt][nt][2*h+1]);
                    *(float2*)(g_y + (size_t)(hbase + r0 + r) * DDIM + col) = v;
                }
            }
        }
}

// ---------------- weighted combine ------------------------------------------
__global__ void combine_kernel(float* __restrict__ out) {
    int t = blockIdx.x;
    int e1 = g_te[2*t], e2 = g_te[2*t+1];
    int s1 = g_off[e1] + g_tp[2*t];
    int s2 = g_off[e2] + g_tp[2*t+1];
    float w1 = g_tw[2*t], w2 = g_tw[2*t+1];
    const float4* a = (const float4*)(g_y + (size_t)s1 * DDIM);
    const float4* b = (const float4*)(g_y + (size_t)s2 * DDIM);
    float4* o = (float4*)(out + (size_t)t * DDIM);
    for (int i = threadIdx.x; i < DDIM / 4; i += blockDim.x) {
        float4 av = a[i], bv = b[i];
        o[i] = make_float4(w1*av.x + w2*bv.x, w1*av.y + w2*bv.y,
                           w1*av.z + w2*bv.z, w1*av.w + w2*bv.w);
    }
}

// ---------------- launch ----------------------------------------------------
extern "C" void kernel_launch(void* const* d_in, const int* in_sizes, int n_in,
                              void* d_out, int out_size) {
    const float* x  = (const float*)d_in[0];
    const float* gw = (const float*)d_in[1];
    const float* wg = (const float*)d_in[2];
    const float* wu = (const float*)d_in[3];
    const float* wd = (const float*)d_in[4];
    float* out = (float*)d_out;

    int T = in_sizes[0] / DDIM;
    int write_logits = (out_size >= T * DDIM + T * NEXP) ? 1 : 0;
    float* logits = out + (size_t)T * DDIM;

    static int smem_set = 0;
    if (!smem_set) {
        cudaFuncSetAttribute(gateup_mma, cudaFuncAttributeMaxDynamicSharedMemorySize, GU_DYN);
        cudaFuncSetAttribute(down_mma,   cudaFuncAttributeMaxDynamicSharedMemorySize, DN_DYN);
        smem_set = 1;
    }

    presplit_kernel<<<(T * DDIM / 4 + 255) / 256, 256>>>(x, T * DDIM / 4);
    router_kernel<<<T, 256>>>(x, gw, logits, write_logits);
    prefix_kernel<<<1, 1>>>();

    int ytiles = (T + 127) / 128;
    dim3 gg(FDIM / 128, ytiles, NEXP);
    gateup_mma<<<gg, 256, GU_DYN>>>(wg, wu);

    dim3 gd(DDIM / 128, ytiles, NEXP);
    down_mma<<<gd, 256, DN_DYN>>>(wd);

    combine_kernel<<<T, 256>>>(out);
}